// round 1
// baseline (speedup 1.0000x reference)
#include <cuda_runtime.h>

// DRP_LAYER: 2D DRP-FDTD, 3 steps, B=2, N=2048.
// E: (B, N+1, N+1), Hx: (B, N-1, N), Hy: (B, N, N-1), all float32.
// Outputs concatenated: E2,Hx2,Hy2,E3,Hx3,Hy3,E4,Hx4,Hy4.

#define NN   2048
#define BB   2
#define CFLc 0.35f

#define ES   (NN + 1)              // 2049 — E row stride
#define HXS  (NN)                  // 2048 — Hx row stride
#define HYS  (NN - 1)              // 2047 — Hy row stride
#define ESZ  ((NN + 1) * (NN + 1))
#define HXSZ ((NN - 1) * NN)
#define HYSZ (NN * (NN - 1))

__device__ float g_coef[2];   // [0]=u = 0.25*beta - 0.1*gamma, [1]=delta

__global__ void coef_kernel(const float* __restrict__ beta,
                            const float* __restrict__ delta,
                            const float* __restrict__ gamma) {
    g_coef[0] = 0.25f * beta[0] - 0.1f * gamma[0];
    g_coef[1] = delta[0];
}

// ---------------------------------------------------------------------------
// Ampere half-step: E_out = E + CFL*(s1 - s2); output grid (N+1)x(N+1)
// ---------------------------------------------------------------------------
__global__ __launch_bounds__(256) void amper_kernel(
    const float* __restrict__ E, const float* __restrict__ Hx,
    const float* __restrict__ Hy, float* __restrict__ Eo)
{
    const int j = blockIdx.x * 32 + threadIdx.x;
    const int i = blockIdx.y * 8  + threadIdx.y;
    if (i > NN || j > NN) return;
    const int b = blockIdx.z;

    const float* __restrict__ e  = E  + (size_t)b * ESZ;
    const float* __restrict__ hx = Hx + (size_t)b * HXSZ;
    const float* __restrict__ hy = Hy + (size_t)b * HYSZ;
    float* __restrict__ eo = Eo + (size_t)b * ESZ;

    const float u  = g_coef[0];
    const float dl = g_coef[1];
    const float c01 = u + dl - 0.5f;     // Kc[0][1]
    const float c11 = -2.0f * dl;        // Kc[1][1]
    const float c21 = dl + 0.5f - u;     // Kc[2][1]
    const float KF0 = -11.0f/6.0f, KF1 = 3.0f, KF2 = -1.5f, KF3 = 1.0f/3.0f;
    const float KB0 = -1.0f/3.0f,  KB1 = 1.5f, KB2 = -3.0f, KB3 = 11.0f/6.0f;

#define HXv(r,c) hx[(r) * HXS + (c)]
#define HYv(r,c) hy[(r) * HYS + (c)]

    const bool iin = (i >= 2) && (i <= NN - 2);
    const bool jin = (j >= 2) && (j <= NN - 2);

    // ---- s1: x-derivative terms from Hy (transposed kernels) ----
    float s1 = 0.0f;
    if (iin && jin) {
        s1 += -u  * HYv(i-2, j-2) + u   * HYv(i-2, j)
            + c01 * HYv(i-1, j-2) + c11 * HYv(i-1, j-1) + c21 * HYv(i-1, j)
            + u   * HYv(i  , j-2) - u   * HYv(i  , j)
            - u   * HYv(i+1, j-2) + u   * HYv(i+1, j);
    }
    if (i >= 1 && j <= NN - 5)
        s1 += KF0*HYv(i-1, j) + KF1*HYv(i-1, j+1) + KF2*HYv(i-1, j+2) + KF3*HYv(i-1, j+3);
    if (i <= NN - 1 && j >= 5)
        s1 += KB0*HYv(i, j-5) + KB1*HYv(i, j-4) + KB2*HYv(i, j-3) + KB3*HYv(i, j-2);
    if (iin && (j == 1 || j == 2))
        s1 += -HYv(i-1, j-1) + 3.0f*HYv(i-1, j) - 3.0f*HYv(i-1, j+1) + HYv(i-1, j+2);
    if (iin && (j == NN-2 || j == NN-1))
        s1 += HYv(i, j-4) - 3.0f*HYv(i, j-3) + 3.0f*HYv(i, j-2) - HYv(i, j-1);

    // ---- s2: y-derivative terms from Hx ----
    float s2 = 0.0f;
    if (iin && jin) {
        s2 += -u  * HXv(i-2, j-2) + c01 * HXv(i-2, j-1) + u * HXv(i-2, j) - u * HXv(i-2, j+1)
            + c11 * HXv(i-1, j-1)
            + u   * HXv(i  , j-2) + c21 * HXv(i  , j-1) - u * HXv(i  , j) + u * HXv(i  , j+1);
    }
    if (i <= NN - 5 && j >= 1)
        s2 += KF0*HXv(i, j-1) + KF1*HXv(i+1, j-1) + KF2*HXv(i+2, j-1) + KF3*HXv(i+3, j-1);
    if (i >= 5 && j <= NN - 1)
        s2 += KB0*HXv(i-5, j) + KB1*HXv(i-4, j) + KB2*HXv(i-3, j) + KB3*HXv(i-2, j);
    if ((i == 1 || i == 2) && jin)
        s2 += -HXv(i-1, j-1) + 3.0f*HXv(i, j-1) - 3.0f*HXv(i+1, j-1) + HXv(i+2, j-1);
    if ((i == NN-2 || i == NN-1) && jin)
        s2 += HXv(i-4, j) - 3.0f*HXv(i-3, j) + 3.0f*HXv(i-2, j) - HXv(i-1, j);

    const int idx = i * ES + j;
    eo[idx] = e[idx] + CFLc * (s1 - s2);
#undef HXv
#undef HYv
}

// ---------------------------------------------------------------------------
// Faraday half-step: Hx_out = Hx - CFL*s3 ; Hy_out = Hy + CFL*s4
// grid covers (i,j) in [0,N-1]^2; Hx valid i<=N-2, Hy valid j<=N-2
// ---------------------------------------------------------------------------
__global__ __launch_bounds__(256) void faraday_kernel(
    const float* __restrict__ E, const float* __restrict__ Hx,
    const float* __restrict__ Hy, float* __restrict__ Hxo,
    float* __restrict__ Hyo)
{
    const int j = blockIdx.x * 32 + threadIdx.x;
    const int i = blockIdx.y * 8  + threadIdx.y;
    if (i >= NN || j >= NN) return;
    const int b = blockIdx.z;

    const float* __restrict__ e  = E  + (size_t)b * ESZ;
    const float* __restrict__ hx = Hx + (size_t)b * HXSZ;
    const float* __restrict__ hy = Hy + (size_t)b * HYSZ;
    float* __restrict__ hxo = Hxo + (size_t)b * HXSZ;
    float* __restrict__ hyo = Hyo + (size_t)b * HYSZ;

    const float u  = g_coef[0];
    const float dl = g_coef[1];
    const float c01 = u + dl - 0.5f;
    const float c11 = -2.0f * dl;
    const float c21 = dl + 0.5f - u;

#define EEv(r,c) e[(r) * ES + (c)]

    // ---- Hx update (s3: y-derivative of E) ----
    if (i <= NN - 2) {
        float s3 = 0.0f;
        if (j >= 1 && j <= NN - 2) {
            s3 += -u  * EEv(i  , j-1) + c01 * EEv(i  , j) + u * EEv(i  , j+1) - u * EEv(i  , j+2)
                + c11 * EEv(i+1, j)
                + u   * EEv(i+2, j-1) + c21 * EEv(i+2, j) - u * EEv(i+2, j+1) + u * EEv(i+2, j+2);
        }
        if (i <= NN - 4)
            s3 += -1.5f * EEv(i+1, j) + 2.0f * EEv(i+2, j) - 0.5f * EEv(i+3, j);
        if (i >= 2)
            s3 +=  0.5f * EEv(i-1, j+1) - 2.0f * EEv(i, j+1) + 1.5f * EEv(i+1, j+1);
        hxo[i * HXS + j] = hx[i * HXS + j] - CFLc * s3;
    }

    // ---- Hy update (s4: x-derivative of E) ----
    if (j <= NN - 2) {
        float s4 = 0.0f;
        if (i >= 1 && i <= NN - 2) {
            s4 += -u  * EEv(i-1, j) + u * EEv(i-1, j+2)
                + c01 * EEv(i  , j) + c11 * EEv(i, j+1) + c21 * EEv(i, j+2)
                + u   * EEv(i+1, j) - u * EEv(i+1, j+2)
                - u   * EEv(i+2, j) + u * EEv(i+2, j+2);
        }
        if (j <= NN - 4)
            s4 += -1.5f * EEv(i, j+1) + 2.0f * EEv(i, j+2) - 0.5f * EEv(i, j+3);
        if (j >= 2)
            s4 +=  0.5f * EEv(i+1, j-1) - 2.0f * EEv(i+1, j) + 1.5f * EEv(i+1, j+1);
        hyo[i * HYS + j] = hy[i * HYS + j] + CFLc * s4;
    }
#undef EEv
}

// ---------------------------------------------------------------------------
extern "C" void kernel_launch(void* const* d_in, const int* in_sizes, int n_in,
                              void* d_out, int out_size)
{
    const float* E0    = (const float*)d_in[0];
    const float* Hx0   = (const float*)d_in[1];
    const float* Hy0   = (const float*)d_in[2];
    const float* beta  = (const float*)d_in[3];
    const float* delta = (const float*)d_in[4];
    const float* gamma = (const float*)d_in[5];

    float* out = (float*)d_out;
    const size_t esz  = (size_t)BB * ESZ;
    const size_t hxsz = (size_t)BB * HXSZ;
    const size_t hysz = (size_t)BB * HYSZ;

    float* E2  = out;
    float* Hx2 = E2  + esz;
    float* Hy2 = Hx2 + hxsz;
    float* E3  = Hy2 + hysz;
    float* Hx3 = E3  + esz;
    float* Hy3 = Hx3 + hxsz;
    float* E4  = Hy3 + hysz;
    float* Hx4 = E4  + esz;
    float* Hy4 = Hx4 + hxsz;

    coef_kernel<<<1, 1>>>(beta, delta, gamma);

    dim3 blk(32, 8, 1);
    dim3 gE((NN + 1 + 31) / 32, (NN + 1 + 7) / 8, BB);   // covers (N+1)^2
    dim3 gH((NN + 31) / 32, (NN + 7) / 8, BB);           // covers N^2

    amper_kernel  <<<gE, blk>>>(E0, Hx0, Hy0, E2);
    faraday_kernel<<<gH, blk>>>(E2, Hx0, Hy0, Hx2, Hy2);

    amper_kernel  <<<gE, blk>>>(E2, Hx2, Hy2, E3);
    faraday_kernel<<<gH, blk>>>(E3, Hx2, Hy2, Hx3, Hy3);

    amper_kernel  <<<gE, blk>>>(E3, Hx3, Hy3, E4);
    faraday_kernel<<<gH, blk>>>(E4, Hx3, Hy3, Hx4, Hy4);
}